// round 11
// baseline (speedup 1.0000x reference)
#include <cuda_runtime.h>
#include <cuda_fp16.h>
#include <cstdint>

// CIN via mma.sync (base-ISA tensor cores).
// out[r,j] = sum_{h,m} xl[r,h]*x0[r,m]*W[h*32+m,j]; r = b*16+d.
// R11: warp tile 64M x 16N (unique N strip per warp -> B ldsm loaded ONCE
//      per CTA), bfr double-buffered ldsm pipeline, register-built A (R10).

namespace {
constexpr int RTOT = 16384;           // 1024 batches * 16 emb rows
constexpr int NOUT = 128;
constexpr int OUTW = 384;
constexpr int TM   = 64;              // rows per CTA (= 4 batches)
constexpr int NCTA = RTOT / TM;       // 256
constexpr int NTHR = 256;
constexpr int KC   = 128;             // K per chunk
constexpr int CHUNK_BYTES = 128 * KC * 2;   // 32768

// SMEM layout (bytes)
constexpr int OFF_B    = 0;                        // 2 stages x 32768
constexpr int OFF_X0   = 65536;                    // float[64][33] = 8448
constexpr int OFF_BIAS = 73984;                    // 512
constexpr int OFF_XL   = 74496;                    // 2 stages x 1024 (float[4][64])
constexpr int OFF_MBAR = 76544;                    // 2 x 8B
constexpr int SMEM_TOTAL = 76560;
}

// device-global scratch (allocation-free rule)
// g_Wt: per layer, chunk-major pre-swizzled byte image:
//   byte off = c*32768 + (kk>>6)*16384 + j*128 + (((kk&63)*2) ^ ((j&7)<<4))
__device__ __align__(128) __half g_Wt[128 * (1024 + 4096 + 4096)];
__device__ __align__(16) float  g_xlA[RTOT * NOUT];  // transposed [col][row]
__device__ __align__(16) float  g_xlB[RTOT * NOUT];

// ---------------- helpers ----------------
__device__ __forceinline__ uint32_t smem_u32(const void* p) {
    uint32_t a;
    asm("{ .reg .u64 t; cvta.to.shared.u64 t, %1; cvt.u32.u64 %0, t; }" : "=r"(a) : "l"(p));
    return a;
}
__device__ __forceinline__ void ldsm4(uint32_t* r, uint32_t addr) {
    asm volatile("ldmatrix.sync.aligned.m8n8.x4.shared.b16 {%0,%1,%2,%3}, [%4];"
                 : "=r"(r[0]), "=r"(r[1]), "=r"(r[2]), "=r"(r[3]) : "r"(addr));
}
__device__ __forceinline__ void mma16816(float* c, const uint32_t* a, const uint32_t* b) {
    asm volatile("mma.sync.aligned.m16n8k16.row.col.f32.f16.f16.f32 "
                 "{%0,%1,%2,%3}, {%4,%5,%6,%7}, {%8,%9}, {%0,%1,%2,%3};"
                 : "+f"(c[0]), "+f"(c[1]), "+f"(c[2]), "+f"(c[3])
                 : "r"(a[0]), "r"(a[1]), "r"(a[2]), "r"(a[3]), "r"(b[0]), "r"(b[1]));
}
__device__ __forceinline__ uint32_t h2u(__half2 h) {
    return *reinterpret_cast<uint32_t*>(&h);
}
#define MBAR_INIT(mb, n) \
    asm volatile("mbarrier.init.shared.b64 [%0], %1;" :: "r"((uint32_t)(mb)), "r"((uint32_t)(n)) : "memory")
#define MBAR_EXPECT_TX(mb, tx) \
    asm volatile("mbarrier.arrive.expect_tx.shared.b64 _, [%0], %1;" :: "r"((uint32_t)(mb)), "r"((uint32_t)(tx)) : "memory")
#define MBAR_WAIT(mb, ph) \
    asm volatile("{\n\t.reg .pred p;\n\t" \
        "WL_%=:\n\t" \
        "mbarrier.try_wait.parity.shared.b64 p, [%0], %1;\n\t" \
        "@!p bra WL_%=;\n\t}" :: "r"((uint32_t)(mb)), "r"((uint32_t)(ph)) : "memory")
#define BULK_CP(dst, src, bytes, mb) \
    asm volatile("cp.async.bulk.shared::cta.global.mbarrier::complete_tx::bytes [%0], [%1], %2, [%3];" \
                 :: "r"((uint32_t)(dst)), "l"(src), "r"((uint32_t)(bytes)), "r"((uint32_t)(mb)) : "memory")

// ---------------- W -> chunk-major pre-swizzled fp16 image ----------------
template <int LAYER>
__global__ void wprep(const float* __restrict__ W) {
    constexpr int WOFF = (LAYER == 0) ? 0 : (LAYER == 1 ? 131072 : 655360);
    char* Wt = reinterpret_cast<char*>(g_Wt + WOFF);
    __shared__ float s[32][129];
    const int k0 = blockIdx.x * 32;
    const int t  = threadIdx.x;
#pragma unroll
    for (int i = 0; i < 16; i++) {
        int idx = t + i * 256;
        int kk = idx >> 7, j = idx & 127;
        s[kk][j] = W[(size_t)(k0 + kk) * 128 + j];
    }
    __syncthreads();
    const int j = t >> 1, hb = t & 1;
    const int c = k0 >> 7;
#pragma unroll
    for (int r = 0; r < 2; r++) {
        uint32_t w[4];
        const int kk = (k0 & 127) + hb * 16 + r * 8;
#pragma unroll
        for (int e = 0; e < 4; e++) {
            int kl = hb * 16 + r * 8 + e * 2;
            __half2 h2 = __floats2half2_rn(s[kl][j], s[kl + 1][j]);
            w[e] = *reinterpret_cast<uint32_t*>(&h2);
        }
        size_t off = (size_t)c * 32768 + (kk >> 6) * 16384 + j * 128
                   + (((uint32_t)(kk & 63) * 2) ^ ((uint32_t)(j & 7) << 4));
        *reinterpret_cast<uint4*>(Wt + off) = make_uint4(w[0], w[1], w[2], w[3]);
    }
}

// ---------------- main layer kernel ----------------
template <int LAYER>
__global__ __launch_bounds__(NTHR, 2)
void cin_mma(const float* __restrict__ inputs,
             const float* __restrict__ bias,
             float* __restrict__ out)
{
    constexpr int  K    = (LAYER == 0) ? 1024 : 4096;
    constexpr int  WOFF = (LAYER == 0) ? 0 : (LAYER == 1 ? 131072 : 655360);
    constexpr int  NC   = K / KC;          // 8 / 32 chunks
    constexpr bool RELU = (LAYER < 2);
    constexpr bool WXL  = (LAYER < 2);

    extern __shared__ char smem[];
    const uint32_t sb = smem_u32(smem);

    const int tid  = threadIdx.x;
    const int wid  = tid >> 5;
    const int lane = tid & 31;
    const int blk  = blockIdx.x;
    const int R0   = blk * TM;

    const char*  Wt     = reinterpret_cast<const char*>(g_Wt + WOFF);
    const float* xl_in  = (LAYER == 2) ? g_xlB : g_xlA;
    float*       xl_out = (LAYER == 0) ? g_xlA : g_xlB;

    // ---- mbarrier init + first B bulk copy ----
    if (tid == 0) {
        MBAR_INIT(sb + OFF_MBAR + 0, 1);
        MBAR_INIT(sb + OFF_MBAR + 8, 1);
    }
    __syncthreads();
    if (tid == 0) {
        MBAR_EXPECT_TX(sb + OFF_MBAR + 0, CHUNK_BYTES);
        BULK_CP(sb + OFF_B, Wt, CHUNK_BYTES, sb + OFF_MBAR + 0);
    }

    // ---- x0 tile (4 batches, contiguous 2048 floats) + bias -> SMEM ----
    {
        const float* src = inputs + (size_t)blk * 2048;
        float* x0sw = reinterpret_cast<float*>(smem + OFF_X0);
#pragma unroll
        for (int i = 0; i < 8; i++) {
            int idx = tid + i * NTHR;
            int bb = idx >> 9, m = (idx >> 4) & 31, d = idx & 15;
            x0sw[(bb * 16 + d) * 33 + m] = src[idx];
        }
        if (tid < 128) reinterpret_cast<float*>(smem + OFF_BIAS)[tid] = bias[tid];
    }

    // ---- xl slice prologue (layers > 0) ----
    float* xls = reinterpret_cast<float*>(smem + OFF_XL);   // [2][4][64]
    const int xh = tid >> 6, xr = tid & 63;
    float xlv = 0.f;
    if (LAYER > 0) {
        xls[tid] = __ldg(&xl_in[(size_t)xh * RTOT + R0 + xr]);      // chunk 0
        if (NC > 1) xlv = __ldg(&xl_in[(size_t)(4 + xh) * RTOT + R0 + xr]);
    }
    __syncthreads();   // x0s, bias, xl stage0 visible

    // ---- per-thread x0 fragment registers: 8 rows x 4 col-pairs ----
    // row(i) = rlow + 8*i (i = mt*2 + s); m = c0 + 8*j + {0,1}
    const int ng = wid;                 // unique 16-col strip per warp
    const int rlow = lane >> 2, c0 = (lane & 3) * 2;
    const int g = lane >> 3;
    const float* x0s = reinterpret_cast<const float*>(smem + OFF_X0);
    __half2 x0p[8][4];
#pragma unroll
    for (int i = 0; i < 8; i++) {
        const int row = rlow + 8 * i;
#pragma unroll
        for (int j = 0; j < 4; j++)
            x0p[i][j] = __floats2half2_rn(x0s[row * 33 + c0 + 8 * j],
                                          x0s[row * 33 + c0 + 8 * j + 1]);
    }

    // ---- accumulators: warp tile 64(M) x 16(N): 4 m-tiles x 2 n-tiles ----
    float acc[4][2][4];
#pragma unroll
    for (int mt = 0; mt < 4; mt++)
#pragma unroll
        for (int nt = 0; nt < 2; nt++)
#pragma unroll
            for (int e = 0; e < 4; e++) acc[mt][nt][e] = 0.f;

    // B ldsm address helper: br fixed per thread, bk varies per ks
    const int br = ng * 16 + (g >> 1) * 8 + (lane & 7);
    auto baddr = [&](uint32_t bbase, int ks) {
        const int bk = ks * 16 + (g & 1) * 8;
        return bbase + (bk >> 6) * 16384 + br * 128
             + (((uint32_t)(bk & 63) * 2) ^ ((br & 7) << 4));
    };

    // ================= main K loop =================
    for (int c = 0; c < NC; c++) {
        const int sA = c & 1;

        MBAR_WAIT(sb + OFF_MBAR + 8 * sA, (c >> 1) & 1);  // B(c) landed
        __syncthreads();   // stage sA^1 consumed (c-1); xl stage (c&1) visible

        if (c + 1 < NC) {
            if (tid == 0) {
                MBAR_EXPECT_TX(sb + OFF_MBAR + 8 * (sA ^ 1), CHUNK_BYTES);
                BULK_CP(sb + OFF_B + (sA ^ 1) * 32768,
                        Wt + (size_t)(c + 1) * CHUNK_BYTES,
                        CHUNK_BYTES, sb + OFF_MBAR + 8 * (sA ^ 1));
            }
            if (LAYER > 0) {
                xls[((c + 1) & 1) * 256 + tid] = xlv;     // stage for c+1
                if (c + 2 < NC)
                    xlv = __ldg(&xl_in[(size_t)((c + 2) * 4 + xh) * RTOT + R0 + xr]);
            }
        }

        const uint32_t bbase = sb + OFF_B + sA * 32768;
        uint32_t bcur[4], bnxt[4];
        ldsm4(bcur, baddr(bbase, 0));           // prologue ldsm

        __half2 xl2[8];
#pragma unroll
        for (int ks = 0; ks < 8; ks++) {
            const int hh = ks >> 1;
            const int jb = (ks & 1) * 2;

            if ((ks & 1) == 0) {                // refresh xl broadcast regs
#pragma unroll
                for (int i = 0; i < 8; i++) {
                    const int row = rlow + 8 * i;
                    float v = (LAYER == 0)
                        ? x0s[row * 33 + c * 4 + hh]
                        : xls[(c & 1) * 256 + hh * 64 + row];
                    xl2[i] = __half2half2(__float2half_rn(v));
                }
            }
            if (ks < 7) ldsm4(bnxt, baddr(bbase, ks + 1));   // prefetch next

#pragma unroll
            for (int mt = 0; mt < 4; mt++) {
                uint32_t afr[4];
                afr[0] = h2u(__hmul2(x0p[mt * 2 + 0][jb],     xl2[mt * 2 + 0]));
                afr[1] = h2u(__hmul2(x0p[mt * 2 + 1][jb],     xl2[mt * 2 + 1]));
                afr[2] = h2u(__hmul2(x0p[mt * 2 + 0][jb + 1], xl2[mt * 2 + 0]));
                afr[3] = h2u(__hmul2(x0p[mt * 2 + 1][jb + 1], xl2[mt * 2 + 1]));
                mma16816(acc[mt][0], afr, bcur);
                mma16816(acc[mt][1], afr, bcur + 2);
            }
#pragma unroll
            for (int e = 0; e < 4; e++) bcur[e] = bnxt[e];
        }
    }

    // ================= epilogue (disjoint 64x16 warp strips) ================
    const float* biass = reinterpret_cast<const float*>(smem + OFF_BIAS);
#pragma unroll
    for (int mt = 0; mt < 4; mt++) {
        const int batch = blk * 4 + mt;              // one m16 tile == one batch
        const int r0 = R0 + mt * 16 + rlow;
#pragma unroll
        for (int nt = 0; nt < 2; nt++) {
            const int j0 = ng * 16 + nt * 8 + (lane & 3) * 2;
            const float b0 = biass[j0], b1 = biass[j0 + 1];
            float v0 = acc[mt][nt][0] + b0;
            float v1 = acc[mt][nt][1] + b1;
            float v2 = acc[mt][nt][2] + b0;
            float v3 = acc[mt][nt][3] + b1;
            if (RELU) {
                v0 = fmaxf(v0, 0.f); v1 = fmaxf(v1, 0.f);
                v2 = fmaxf(v2, 0.f); v3 = fmaxf(v3, 0.f);
            }
            if (WXL) {
                xl_out[(size_t)j0 * RTOT + r0]           = v0;
                xl_out[(size_t)(j0 + 1) * RTOT + r0]     = v1;
                xl_out[(size_t)j0 * RTOT + r0 + 8]       = v2;
                xl_out[(size_t)(j0 + 1) * RTOT + r0 + 8] = v3;
            }
            float s0 = v0 + v2, s1 = v1 + v3;        // rows r, r+8
            s0 += __shfl_xor_sync(0xffffffffu, s0, 4);
            s1 += __shfl_xor_sync(0xffffffffu, s1, 4);
            s0 += __shfl_xor_sync(0xffffffffu, s0, 8);
            s1 += __shfl_xor_sync(0xffffffffu, s1, 8);
            s0 += __shfl_xor_sync(0xffffffffu, s0, 16);
            s1 += __shfl_xor_sync(0xffffffffu, s1, 16);
            if (lane < 4) {
                float* dst = out + (size_t)batch * OUTW + LAYER * NOUT
                           + ng * 16 + nt * 8 + lane * 2;
                dst[0] = s0;
                dst[1] = s1;
            }
        }
    }
}

// ---------------- host ----------------
extern "C" void kernel_launch(void* const* d_in, const int* in_sizes, int n_in,
                              void* d_out, int out_size)
{
    const float* inputs = (const float*)d_in[0];
    const float* W0     = (const float*)d_in[1];
    const float* b0     = (const float*)d_in[2];
    const float* W1     = (const float*)d_in[3];
    const float* b1     = (const float*)d_in[4];
    const float* W2     = (const float*)d_in[5];
    const float* b2     = (const float*)d_in[6];
    float* out = (float*)d_out;

    cudaFuncSetAttribute(cin_mma<0>, cudaFuncAttributeMaxDynamicSharedMemorySize, SMEM_TOTAL);
    cudaFuncSetAttribute(cin_mma<1>, cudaFuncAttributeMaxDynamicSharedMemorySize, SMEM_TOTAL);
    cudaFuncSetAttribute(cin_mma<2>, cudaFuncAttributeMaxDynamicSharedMemorySize, SMEM_TOTAL);

    wprep<0><<<32,  256>>>(W0);
    wprep<1><<<128, 256>>>(W1);
    wprep<2><<<128, 256>>>(W2);

    cin_mma<0><<<NCTA, NTHR, SMEM_TOTAL>>>(inputs, b0, out);
    cin_mma<1><<<NCTA, NTHR, SMEM_TOTAL>>>(inputs, b1, out);
    cin_mma<2><<<NCTA, NTHR, SMEM_TOTAL>>>(inputs, b2, out);
}

// round 12
// speedup vs baseline: 1.1542x; 1.1542x over previous
#include <cuda_runtime.h>
#include <cuda_fp16.h>
#include <cstdint>

// CIN via mma.sync (base-ISA tensor cores).
// out[r,j] = sum_{h,m} xl[r,h]*x0[r,m]*W[h*32+m,j]; r = b*16+d.
// R12: R10 layout (warp tile 32Mx32N, register-built A, bulk-copied B)
//      + B-fragment double-buffered ldsm pipeline + merged wprep.

namespace {
constexpr int RTOT = 16384;           // 1024 batches * 16 emb rows
constexpr int NOUT = 128;
constexpr int OUTW = 384;
constexpr int TM   = 64;              // rows per CTA (= 4 batches)
constexpr int NCTA = RTOT / TM;       // 256
constexpr int NTHR = 256;
constexpr int KC   = 128;             // K per chunk
constexpr int CHUNK_BYTES = 128 * KC * 2;   // 32768

// SMEM layout (bytes)
constexpr int OFF_B    = 0;                        // 2 stages x 32768
constexpr int OFF_X0   = 65536;                    // float[64][33] = 8448
constexpr int OFF_BIAS = 73984;                    // 512
constexpr int OFF_XL   = 74496;                    // 2 stages x 1024 (float[4][64])
constexpr int OFF_MBAR = 76544;                    // 2 x 8B
constexpr int SMEM_TOTAL = 76560;
}

// device-global scratch (allocation-free rule)
// g_Wt: per layer, chunk-major pre-swizzled byte image:
//   byte off = c*32768 + (kk>>6)*16384 + j*128 + (((kk&63)*2) ^ ((j&7)<<4))
__device__ __align__(128) __half g_Wt[128 * (1024 + 4096 + 4096)];
__device__ __align__(16) float  g_xlA[RTOT * NOUT];  // transposed [col][row]
__device__ __align__(16) float  g_xlB[RTOT * NOUT];

// ---------------- helpers ----------------
__device__ __forceinline__ uint32_t smem_u32(const void* p) {
    uint32_t a;
    asm("{ .reg .u64 t; cvta.to.shared.u64 t, %1; cvt.u32.u64 %0, t; }" : "=r"(a) : "l"(p));
    return a;
}
__device__ __forceinline__ void ldsm4(uint32_t* r, uint32_t addr) {
    asm volatile("ldmatrix.sync.aligned.m8n8.x4.shared.b16 {%0,%1,%2,%3}, [%4];"
                 : "=r"(r[0]), "=r"(r[1]), "=r"(r[2]), "=r"(r[3]) : "r"(addr));
}
__device__ __forceinline__ void mma16816(float* c, const uint32_t* a, const uint32_t* b) {
    asm volatile("mma.sync.aligned.m16n8k16.row.col.f32.f16.f16.f32 "
                 "{%0,%1,%2,%3}, {%4,%5,%6,%7}, {%8,%9}, {%0,%1,%2,%3};"
                 : "+f"(c[0]), "+f"(c[1]), "+f"(c[2]), "+f"(c[3])
                 : "r"(a[0]), "r"(a[1]), "r"(a[2]), "r"(a[3]), "r"(b[0]), "r"(b[1]));
}
__device__ __forceinline__ uint32_t h2u(__half2 h) {
    return *reinterpret_cast<uint32_t*>(&h);
}
#define MBAR_INIT(mb, n) \
    asm volatile("mbarrier.init.shared.b64 [%0], %1;" :: "r"((uint32_t)(mb)), "r"((uint32_t)(n)) : "memory")
#define MBAR_EXPECT_TX(mb, tx) \
    asm volatile("mbarrier.arrive.expect_tx.shared.b64 _, [%0], %1;" :: "r"((uint32_t)(mb)), "r"((uint32_t)(tx)) : "memory")
#define MBAR_WAIT(mb, ph) \
    asm volatile("{\n\t.reg .pred p;\n\t" \
        "WL_%=:\n\t" \
        "mbarrier.try_wait.parity.shared.b64 p, [%0], %1;\n\t" \
        "@!p bra WL_%=;\n\t}" :: "r"((uint32_t)(mb)), "r"((uint32_t)(ph)) : "memory")
#define BULK_CP(dst, src, bytes, mb) \
    asm volatile("cp.async.bulk.shared::cta.global.mbarrier::complete_tx::bytes [%0], [%1], %2, [%3];" \
                 :: "r"((uint32_t)(dst)), "l"(src), "r"((uint32_t)(bytes)), "r"((uint32_t)(mb)) : "memory")

// ---------------- W -> chunk-major pre-swizzled fp16 image (all layers) ----
// blocks 0..31 -> layer0, 32..159 -> layer1, 160..287 -> layer2
__global__ void wprep_all(const float* __restrict__ W0,
                          const float* __restrict__ W1,
                          const float* __restrict__ W2) {
    const int b = blockIdx.x;
    const float* W;
    char* Wt;
    int kb;                                       // k-block within layer
    if (b < 32)       { W = W0; Wt = reinterpret_cast<char*>(g_Wt);          kb = b; }
    else if (b < 160) { W = W1; Wt = reinterpret_cast<char*>(g_Wt + 131072); kb = b - 32; }
    else              { W = W2; Wt = reinterpret_cast<char*>(g_Wt + 655360); kb = b - 160; }

    __shared__ float s[32][129];
    const int k0 = kb * 32;
    const int t  = threadIdx.x;
#pragma unroll
    for (int i = 0; i < 16; i++) {
        int idx = t + i * 256;
        int kk = idx >> 7, j = idx & 127;
        s[kk][j] = W[(size_t)(k0 + kk) * 128 + j];
    }
    __syncthreads();
    const int j = t >> 1, hb = t & 1;
    const int c = k0 >> 7;
#pragma unroll
    for (int r = 0; r < 2; r++) {
        uint32_t w[4];
        const int kk = (k0 & 127) + hb * 16 + r * 8;
#pragma unroll
        for (int e = 0; e < 4; e++) {
            int kl = hb * 16 + r * 8 + e * 2;
            __half2 h2 = __floats2half2_rn(s[kl][j], s[kl + 1][j]);
            w[e] = *reinterpret_cast<uint32_t*>(&h2);
        }
        size_t off = (size_t)c * 32768 + (kk >> 6) * 16384 + j * 128
                   + (((uint32_t)(kk & 63) * 2) ^ ((uint32_t)(j & 7) << 4));
        *reinterpret_cast<uint4*>(Wt + off) = make_uint4(w[0], w[1], w[2], w[3]);
    }
}

// ---------------- main layer kernel ----------------
template <int LAYER>
__global__ __launch_bounds__(NTHR, 2)
void cin_mma(const float* __restrict__ inputs,
             const float* __restrict__ bias,
             float* __restrict__ out)
{
    constexpr int  K    = (LAYER == 0) ? 1024 : 4096;
    constexpr int  WOFF = (LAYER == 0) ? 0 : (LAYER == 1 ? 131072 : 655360);
    constexpr int  NC   = K / KC;          // 8 / 32 chunks
    constexpr bool RELU = (LAYER < 2);
    constexpr bool WXL  = (LAYER < 2);

    extern __shared__ char smem[];
    const uint32_t sb = smem_u32(smem);

    const int tid  = threadIdx.x;
    const int wid  = tid >> 5;
    const int lane = tid & 31;
    const int blk  = blockIdx.x;
    const int R0   = blk * TM;

    const char*  Wt     = reinterpret_cast<const char*>(g_Wt + WOFF);
    const float* xl_in  = (LAYER == 2) ? g_xlB : g_xlA;
    float*       xl_out = (LAYER == 0) ? g_xlA : g_xlB;

    // ---- mbarrier init + first B bulk copy ----
    if (tid == 0) {
        MBAR_INIT(sb + OFF_MBAR + 0, 1);
        MBAR_INIT(sb + OFF_MBAR + 8, 1);
    }
    __syncthreads();
    if (tid == 0) {
        MBAR_EXPECT_TX(sb + OFF_MBAR + 0, CHUNK_BYTES);
        BULK_CP(sb + OFF_B, Wt, CHUNK_BYTES, sb + OFF_MBAR + 0);
    }

    // ---- x0 tile (4 batches, contiguous 2048 floats) + bias -> SMEM ----
    {
        const float* src = inputs + (size_t)blk * 2048;
        float* x0sw = reinterpret_cast<float*>(smem + OFF_X0);
#pragma unroll
        for (int i = 0; i < 8; i++) {
            int idx = tid + i * NTHR;
            int bb = idx >> 9, m = (idx >> 4) & 31, d = idx & 15;
            x0sw[(bb * 16 + d) * 33 + m] = src[idx];
        }
        if (tid < 128) reinterpret_cast<float*>(smem + OFF_BIAS)[tid] = bias[tid];
    }

    // ---- xl slice prologue (layers > 0): stage0 + prefetch chunk1 ----
    float* xls = reinterpret_cast<float*>(smem + OFF_XL);   // [2][4][64]
    const int xh = tid >> 6, xr = tid & 63;
    float xlv = 0.f;
    if (LAYER > 0) {
        xls[tid] = __ldg(&xl_in[(size_t)xh * RTOT + R0 + xr]);      // chunk 0
        if (NC > 1) xlv = __ldg(&xl_in[(size_t)(4 + xh) * RTOT + R0 + xr]);
    }
    __syncthreads();   // x0s, bias, xl stage0 visible

    // ---- per-thread x0 fragment registers ----
    const int mg = wid >> 2, ng = wid & 3;
    const int rlow = lane >> 2, c0 = (lane & 3) * 2;
    const int g = lane >> 3;
    const float* x0s = reinterpret_cast<const float*>(smem + OFF_X0);
    __half2 x0p[4][4];
    int rowv[4];
#pragma unroll
    for (int rr = 0; rr < 4; rr++) {
        const int mt = rr >> 1, s = rr & 1;
        const int row = mg * 32 + mt * 16 + rlow + s * 8;
        rowv[rr] = row;
#pragma unroll
        for (int j = 0; j < 4; j++)
            x0p[rr][j] = __floats2half2_rn(x0s[row * 33 + c0 + 8 * j],
                                           x0s[row * 33 + c0 + 8 * j + 1]);
    }

    // ---- accumulators: warp tile 32(M) x 32(N); warps = 2M x 4N ----
    float acc[2][4][4];
#pragma unroll
    for (int mt = 0; mt < 2; mt++)
#pragma unroll
        for (int nt = 0; nt < 4; nt++)
#pragma unroll
            for (int e = 0; e < 4; e++) acc[mt][nt][e] = 0.f;

    // B ldsm addressing: two tiles (bt=0,1), fixed rows, bk varies per ks
    const int br0 = ng * 32 + (g >> 1) * 8 + (lane & 7);
    const int br1 = br0 + 16;
    auto baddr = [&](uint32_t bbase, int br, int ks) {
        const int bk = ks * 16 + (g & 1) * 8;
        return bbase + (bk >> 6) * 16384 + br * 128
             + (((uint32_t)(bk & 63) * 2) ^ ((br & 7) << 4));
    };

    // ================= main K loop =================
    for (int c = 0; c < NC; c++) {
        const int sA = c & 1;

        MBAR_WAIT(sb + OFF_MBAR + 8 * sA, (c >> 1) & 1);  // B(c) landed
        __syncthreads();   // stage sA^1 consumed (c-1); xl stage (c&1) visible

        if (c + 1 < NC) {
            if (tid == 0) {
                MBAR_EXPECT_TX(sb + OFF_MBAR + 8 * (sA ^ 1), CHUNK_BYTES);
                BULK_CP(sb + OFF_B + (sA ^ 1) * 32768,
                        Wt + (size_t)(c + 1) * CHUNK_BYTES,
                        CHUNK_BYTES, sb + OFF_MBAR + 8 * (sA ^ 1));
            }
            if (LAYER > 0) {
                xls[((c + 1) & 1) * 256 + tid] = xlv;     // stage for c+1
                if (c + 2 < NC)
                    xlv = __ldg(&xl_in[(size_t)((c + 2) * 4 + xh) * RTOT + R0 + xr]);
            }
        }

        // ---- xl broadcast regs for this chunk: 4 rows x 4 h ----
        __half2 xl2[4][4];
#pragma unroll
        for (int rr = 0; rr < 4; rr++) {
#pragma unroll
            for (int hh = 0; hh < 4; hh++) {
                float v = (LAYER == 0)
                    ? x0s[rowv[rr] * 33 + c * 4 + hh]
                    : xls[(c & 1) * 256 + hh * 64 + rowv[rr]];
                xl2[rr][hh] = __half2half2(__float2half_rn(v));
            }
        }

        // ---- compute chunk c: 8 k16 steps; B frags double-buffered ----
        const uint32_t bbase = sb + OFF_B + sA * 32768;
        uint32_t bcur[8], bnxt[8];
        ldsm4(bcur,     baddr(bbase, br0, 0));    // prologue: ks=0 frags
        ldsm4(bcur + 4, baddr(bbase, br1, 0));
#pragma unroll
        for (int ks = 0; ks < 8; ks++) {
            if (ks < 7) {                          // prefetch ks+1 before mma
                ldsm4(bnxt,     baddr(bbase, br0, ks + 1));
                ldsm4(bnxt + 4, baddr(bbase, br1, ks + 1));
            }
            const int hh = ks >> 1;
            const int jb = (ks & 1) * 2;
            uint32_t afr[2][4];
#pragma unroll
            for (int mt = 0; mt < 2; mt++) {
                afr[mt][0] = h2u(__hmul2(x0p[mt * 2 + 0][jb],     xl2[mt * 2 + 0][hh]));
                afr[mt][1] = h2u(__hmul2(x0p[mt * 2 + 1][jb],     xl2[mt * 2 + 1][hh]));
                afr[mt][2] = h2u(__hmul2(x0p[mt * 2 + 0][jb + 1], xl2[mt * 2 + 0][hh]));
                afr[mt][3] = h2u(__hmul2(x0p[mt * 2 + 1][jb + 1], xl2[mt * 2 + 1][hh]));
            }
#pragma unroll
            for (int mt = 0; mt < 2; mt++)
#pragma unroll
                for (int nt = 0; nt < 4; nt++)
                    mma16816(acc[mt][nt], afr[mt], bcur + nt * 2);
#pragma unroll
            for (int e = 0; e < 8; e++) bcur[e] = bnxt[e];
        }
    }

    // ================= epilogue (disjoint 32x32 tiles) ======================
    const float* biass = reinterpret_cast<const float*>(smem + OFF_BIAS);
#pragma unroll
    for (int mt = 0; mt < 2; mt++) {
        const int batch = blk * 4 + mg * 2 + mt;     // one m16 tile == one batch
        const int r0 = R0 + mg * 32 + mt * 16 + rlow;
#pragma unroll
        for (int nt = 0; nt < 4; nt++) {
            const int j0 = ng * 32 + nt * 8 + (lane & 3) * 2;
            const float b0 = biass[j0], b1 = biass[j0 + 1];
            float v0 = acc[mt][nt][0] + b0;
            float v1 = acc[mt][nt][1] + b1;
            float v2 = acc[mt][nt][2] + b0;
            float v3 = acc[mt][nt][3] + b1;
            if (RELU) {
                v0 = fmaxf(v0, 0.f); v1 = fmaxf(v1, 0.f);
                v2 = fmaxf(v2, 0.f); v3 = fmaxf(v3, 0.f);
            }
            if (WXL) {
                xl_out[(size_t)j0 * RTOT + r0]           = v0;
                xl_out[(size_t)(j0 + 1) * RTOT + r0]     = v1;
                xl_out[(size_t)j0 * RTOT + r0 + 8]       = v2;
                xl_out[(size_t)(j0 + 1) * RTOT + r0 + 8] = v3;
            }
            float s0 = v0 + v2, s1 = v1 + v3;        // rows r, r+8
            s0 += __shfl_xor_sync(0xffffffffu, s0, 4);
            s1 += __shfl_xor_sync(0xffffffffu, s1, 4);
            s0 += __shfl_xor_sync(0xffffffffu, s0, 8);
            s1 += __shfl_xor_sync(0xffffffffu, s1, 8);
            s0 += __shfl_xor_sync(0xffffffffu, s0, 16);
            s1 += __shfl_xor_sync(0xffffffffu, s1, 16);
            if (lane < 4) {
                float* dst = out + (size_t)batch * OUTW + LAYER * NOUT
                           + ng * 32 + nt * 8 + lane * 2;
                dst[0] = s0;
                dst[1] = s1;
            }
        }
    }
}

// ---------------- host ----------------
extern "C" void kernel_launch(void* const* d_in, const int* in_sizes, int n_in,
                              void* d_out, int out_size)
{
    const float* inputs = (const float*)d_in[0];
    const float* W0     = (const float*)d_in[1];
    const float* b0     = (const float*)d_in[2];
    const float* W1     = (const float*)d_in[3];
    const float* b1     = (const float*)d_in[4];
    const float* W2     = (const float*)d_in[5];
    const float* b2     = (const float*)d_in[6];
    float* out = (float*)d_out;

    cudaFuncSetAttribute(cin_mma<0>, cudaFuncAttributeMaxDynamicSharedMemorySize, SMEM_TOTAL);
    cudaFuncSetAttribute(cin_mma<1>, cudaFuncAttributeMaxDynamicSharedMemorySize, SMEM_TOTAL);
    cudaFuncSetAttribute(cin_mma<2>, cudaFuncAttributeMaxDynamicSharedMemorySize, SMEM_TOTAL);

    wprep_all<<<288, 256>>>(W0, W1, W2);

    cin_mma<0><<<NCTA, NTHR, SMEM_TOTAL>>>(inputs, b0, out);
    cin_mma<1><<<NCTA, NTHR, SMEM_TOTAL>>>(inputs, b1, out);
    cin_mma<2><<<NCTA, NTHR, SMEM_TOTAL>>>(inputs, b2, out);
}